// round 7
// baseline (speedup 1.0000x reference)
#include <cuda_runtime.h>
#include <math_constants.h>

#define DDIM 128
#define KCODES 1024
#define TM 64
#define KC 128
#define NTHREADS 256

// scratch (device globals -- no allocations allowed)
__device__ __align__(16) float g_Bt[DDIM * KCODES];   // transposed codebook [d][k]
__device__ float g_cnorm[KCODES];                     // ||e_k||^2 (full, fp32)
__device__ int   g_counts[KCODES];                    // usage histogram
__device__ float g_partials[2048];                    // per-block loss partials

// ---------------------------------------------------------------------------
// setup: transpose codebook, compute full norms, zero histogram
// grid = (1024), block = (128)
__global__ void vq_setup(const float* __restrict__ emb) {
    int k = blockIdx.x;
    int d = threadIdx.x;
    float v = emb[k * DDIM + d];
    g_Bt[d * KCODES + k] = v;
    float s = v * v;
    #pragma unroll
    for (int o = 16; o > 0; o >>= 1) s += __shfl_xor_sync(0xffffffffu, s, o);
    __shared__ float ws[4];
    if ((threadIdx.x & 31) == 0) ws[threadIdx.x >> 5] = s;
    __syncthreads();
    if (threadIdx.x == 0) {
        float tot = (ws[0] + ws[1]) + (ws[2] + ws[3]);
        g_cnorm[k] = tot;            // FULL norm (reference adds ||e||^2)
        g_counts[k] = 0;
    }
}

// ---------------------------------------------------------------------------
// main: fused score-GEMM + argmin + gather + STE + loss partial + histogram
// grid = N/TM blocks, 256 threads, 96KB dynamic smem
__global__ __launch_bounds__(NTHREADS, 2) void vq_main(
    const float* __restrict__ x, const float* __restrict__ emb,
    float* __restrict__ out, int N) {
    extern __shared__ float smem[];
    float* As = smem;                 // [TM][DDIM]  32KB, kept for epilogue
    float* Bs = smem + TM * DDIM;     // [DDIM][KC]  64KB, reused for reduction

    __shared__ float sP[NTHREADS];    // row-norm partials
    __shared__ float sN[TM];          // per-row ||x||^2 (deterministic)
    __shared__ float wsum[8];

    int tid = threadIdx.x;
    long long row0 = (long long)blockIdx.x * TM;

    // load A tile (contiguous 32KB, coalesced float4)
    {
        const float4* xg = (const float4*)(x + row0 * DDIM);
        float4* As4 = (float4*)As;
        #pragma unroll
        for (int i = 0; i < (TM * DDIM / 4) / NTHREADS; i++)
            As4[tid + i * NTHREADS] = xg[tid + i * NTHREADS];
    }
    __syncthreads();

    // deterministic per-row ||x||^2: 4 threads/row, 32 elems each (ascending),
    // then one thread combines the 4 partials in fixed order.
    {
        int r = tid >> 2, sub = tid & 3;
        const float* ar = As + r * DDIM + sub * 32;
        float s = 0.f;
        #pragma unroll
        for (int i = 0; i < 32; i++) s += ar[i] * ar[i];
        sP[tid] = s;
    }
    __syncthreads();
    if (tid < TM) {
        float s = ((sP[tid * 4 + 0] + sP[tid * 4 + 1]) + sP[tid * 4 + 2]) + sP[tid * 4 + 3];
        sN[tid] = s;
    }
    __syncthreads();

    int ty = tid >> 4;   // 16 row-groups (4 rows each)
    int tx = tid & 15;   // 16 code-groups (8 codes each)
    const float* Ab = As + ty * 4 * DDIM;
    const float* Bb = Bs + tx * 8;

    float Sreg[4];
    #pragma unroll
    for (int m = 0; m < 4; m++) Sreg[m] = sN[ty * 4 + m];

    float best[4];
    int   bidx[4];
    #pragma unroll
    for (int m = 0; m < 4; m++) { best[m] = CUDART_INF_F; bidx[m] = 0x7fffffff; }

    for (int kc = 0; kc < KCODES; kc += KC) {
        __syncthreads();   // protect Bs from previous chunk's readers
        {
            float4* Bs4 = (float4*)Bs;
            #pragma unroll
            for (int i = 0; i < (DDIM * KC / 4) / NTHREADS; i++) {
                int idx4 = tid + i * NTHREADS;
                int d = idx4 >> 5, c4 = idx4 & 31;
                Bs4[idx4] = *(const float4*)(g_Bt + d * KCODES + kc + c4 * 4);
            }
        }
        __syncthreads();

        float acc[4][8];
        #pragma unroll
        for (int m = 0; m < 4; m++)
            #pragma unroll
            for (int j = 0; j < 8; j++) acc[m][j] = 0.f;

        // sequential k-ascending FFMA chain per (row, code) -- matches the
        // reference GEMM's per-element accumulation structure
        #pragma unroll 2
        for (int d = 0; d < DDIM; d += 4) {
            float a[4][4];
            #pragma unroll
            for (int m = 0; m < 4; m++)
                *(float4*)a[m] = *(const float4*)(Ab + m * DDIM + d);
            #pragma unroll
            for (int dd = 0; dd < 4; dd++) {
                float4 bl = *(const float4*)(Bb + (d + dd) * KC);
                float4 bh = *(const float4*)(Bb + (d + dd) * KC + 4);
                #pragma unroll
                for (int m = 0; m < 4; m++) {
                    float av = a[m][dd];
                    acc[m][0] += av * bl.x; acc[m][1] += av * bl.y;
                    acc[m][2] += av * bl.z; acc[m][3] += av * bl.w;
                    acc[m][4] += av * bh.x; acc[m][5] += av * bh.y;
                    acc[m][6] += av * bh.z; acc[m][7] += av * bh.w;
                }
            }
        }

        // replicate reference rounding EXACTLY:
        //   d = fl32( fl32(||x||^2 + ||e||^2) - 2*dot )
        // __fadd_rn/__fsub_rn block FMA contraction. argmin, first-index ties.
        #pragma unroll
        for (int j = 0; j < 8; j++) {
            int kk = kc + tx * 8 + j;
            float cn = g_cnorm[kk];
            #pragma unroll
            for (int m = 0; m < 4; m++) {
                float dist = __fsub_rn(__fadd_rn(Sreg[m], cn), 2.0f * acc[m][j]);
                if (dist < best[m]) { best[m] = dist; bidx[m] = kk; }
            }
        }
    }

    // cross-tx argmin reduction (scratch in Bs region; As stays live)
    __syncthreads();
    float* rval = Bs;
    int* ridx   = (int*)(Bs + TM * 16);
    int* sbest  = (int*)(Bs + 2 * TM * 16);
    #pragma unroll
    for (int m = 0; m < 4; m++) {
        rval[(ty * 4 + m) * 16 + tx] = best[m];
        ridx[(ty * 4 + m) * 16 + tx] = bidx[m];
    }
    __syncthreads();
    if (tid < TM) {
        float bv = CUDART_INF_F; int bi = 0x7fffffff;
        #pragma unroll
        for (int t = 0; t < 16; t++) {
            float v = rval[tid * 16 + t];
            int ii  = ridx[tid * 16 + t];
            if (v < bv || (v == bv && ii < bi)) { bv = v; bi = ii; }
        }
        sbest[tid] = bi;
        atomicAdd(&g_counts[bi], 1);
    }
    __syncthreads();

    // gather codebook row, STE output x + (e - x), accumulate (e - x)^2
    int m   = tid >> 2;
    int sub = tid & 3;
    int brow = sbest[m];
    const float4* ev = (const float4*)(emb + (long long)brow * DDIM);
    const float4* xv = (const float4*)(As + m * DDIM);
    float4* ov = (float4*)(out + (row0 + m) * DDIM);
    float lsum = 0.f;
    #pragma unroll
    for (int i = sub; i < DDIM / 4; i += 4) {
        float4 e4 = __ldg(&ev[i]);
        float4 x4 = xv[i];
        float dx = e4.x - x4.x, dy = e4.y - x4.y;
        float dz = e4.z - x4.z, dw = e4.w - x4.w;
        ov[i] = make_float4(x4.x + dx, x4.y + dy, x4.z + dz, x4.w + dw);
        lsum += dx * dx + dy * dy + dz * dz + dw * dw;
    }
    // deterministic block reduction of loss partial
    #pragma unroll
    for (int o = 16; o > 0; o >>= 1) lsum += __shfl_xor_sync(0xffffffffu, lsum, o);
    if ((tid & 31) == 0) wsum[tid >> 5] = lsum;
    __syncthreads();
    if (tid == 0) {
        float s = 0.f;
        #pragma unroll
        for (int w = 0; w < 8; w++) s += wsum[w];
        g_partials[blockIdx.x] = s;
    }
}

// ---------------------------------------------------------------------------
// finalize: loss scalar + perplexity scalar
// grid = 1 block of 1024 threads
__global__ void vq_finalize(float* __restrict__ out, int n_elems, int N,
                            int blocks, int out_size) {
    __shared__ float buf[1024];
    int t = threadIdx.x;

    float s = 0.f;
    for (int i = t; i < blocks; i += 1024) s += g_partials[i];
    buf[t] = s;
    __syncthreads();
    #pragma unroll
    for (int o = 512; o > 0; o >>= 1) {
        if (t < o) buf[t] += buf[t + o];
        __syncthreads();
    }
    float lsum = buf[0];
    __syncthreads();

    float p = (float)g_counts[t] * (1.0f / (float)N);
    buf[t] = p * logf(p + 1e-10f);
    __syncthreads();
    #pragma unroll
    for (int o = 512; o > 0; o >>= 1) {
        if (t < o) buf[t] += buf[t + o];
        __syncthreads();
    }

    if (t == 0 && out_size >= n_elems + 2) {
        float mean = lsum / (float)n_elems;
        out[n_elems]     = mean + 0.25f * mean;   // q_latent + 0.25*e_latent
        out[n_elems + 1] = expf(-buf[0]);         // perplexity
    }
}

// ---------------------------------------------------------------------------
extern "C" void kernel_launch(void* const* d_in, const int* in_sizes, int n_in,
                              void* d_out, int out_size) {
    const float* x   = (const float*)d_in[0];   // inputs  [16,1024,512] f32
    const float* emb = (const float*)d_in[1];   // codebook [1024,128] f32
    float* out = (float*)d_out;

    int n_elems = in_sizes[0];        // 8388608
    int N = n_elems / DDIM;           // 65536 rows
    int blocks = N / TM;              // 1024

    size_t smem_bytes = (size_t)(TM * DDIM + DDIM * KC) * sizeof(float); // 96KB
    cudaFuncSetAttribute(vq_main, cudaFuncAttributeMaxDynamicSharedMemorySize,
                         (int)smem_bytes);

    vq_setup<<<KCODES, DDIM>>>(emb);
    vq_main<<<blocks, NTHREADS, smem_bytes>>>(x, emb, out, N);
    vq_finalize<<<1, 1024>>>(out, n_elems, N, blocks, out_size);
}

// round 12
// speedup vs baseline: 1.0020x; 1.0020x over previous
#include <cuda_runtime.h>
#include <math_constants.h>

#define DDIM 128
#define KCODES 1024
#define TM 64
#define KC 128
#define NTHREADS 256

// scratch (device globals -- no allocations allowed)
__device__ __align__(16) float g_Bt[DDIM * KCODES];   // transposed codebook [d][k]
__device__ float g_cnorm[KCODES];                     // ||e_k||^2 (full, fp32)
__device__ int   g_counts[KCODES];                    // usage histogram
__device__ float g_partials[2048];                    // per-block loss partials

// ---- packed f32x2 helpers (two independent rn-rounded fp32 FMAs per inst) ----
__device__ __forceinline__ unsigned long long pack2(float v) {
    unsigned long long r;
    asm("mov.b64 %0, {%1, %1};" : "=l"(r) : "r"(__float_as_uint(v)));
    return r;
}
__device__ __forceinline__ unsigned long long ffma2(unsigned long long a,
                                                    unsigned long long b,
                                                    unsigned long long c) {
    unsigned long long d;
    asm("fma.rn.f32x2 %0, %1, %2, %3;" : "=l"(d) : "l"(a), "l"(b), "l"(c));
    return d;
}
__device__ __forceinline__ void unpack2(unsigned long long v, float& lo, float& hi) {
    unsigned int l, h;
    asm("mov.b64 {%0, %1}, %2;" : "=r"(l), "=r"(h) : "l"(v));
    lo = __uint_as_float(l);
    hi = __uint_as_float(h);
}

// ---------------------------------------------------------------------------
// setup: transpose codebook, compute full norms, zero histogram
// grid = (1024), block = (128)
__global__ void vq_setup(const float* __restrict__ emb) {
    int k = blockIdx.x;
    int d = threadIdx.x;
    float v = emb[k * DDIM + d];
    g_Bt[d * KCODES + k] = v;
    float s = v * v;
    #pragma unroll
    for (int o = 16; o > 0; o >>= 1) s += __shfl_xor_sync(0xffffffffu, s, o);
    __shared__ float ws[4];
    if ((threadIdx.x & 31) == 0) ws[threadIdx.x >> 5] = s;
    __syncthreads();
    if (threadIdx.x == 0) {
        float tot = (ws[0] + ws[1]) + (ws[2] + ws[3]);
        g_cnorm[k] = tot;            // FULL norm (reference adds ||e||^2)
        g_counts[k] = 0;
    }
}

// ---------------------------------------------------------------------------
// main: fused score-GEMM (FFMA2) + argmin + gather + STE + loss + histogram
// grid = N/TM blocks, 256 threads, 96KB dynamic smem
__global__ __launch_bounds__(NTHREADS, 2) void vq_main(
    const float* __restrict__ x, const float* __restrict__ emb,
    float* __restrict__ out, int N) {
    extern __shared__ float smem[];
    float* As = smem;                 // [TM][DDIM]  32KB, kept for epilogue
    float* Bs = smem + TM * DDIM;     // [DDIM][KC]  64KB, reused for reduction

    __shared__ float sP[NTHREADS];    // row-norm partials
    __shared__ float sN[TM];          // per-row ||x||^2 (deterministic)
    __shared__ float wsum[8];

    int tid = threadIdx.x;
    long long row0 = (long long)blockIdx.x * TM;

    // load A tile (contiguous 32KB, coalesced float4)
    {
        const float4* xg = (const float4*)(x + row0 * DDIM);
        float4* As4 = (float4*)As;
        #pragma unroll
        for (int i = 0; i < (TM * DDIM / 4) / NTHREADS; i++)
            As4[tid + i * NTHREADS] = xg[tid + i * NTHREADS];
    }
    __syncthreads();

    // deterministic per-row ||x||^2: 4 threads/row, 32 elems each (ascending),
    // then one thread combines the 4 partials in fixed order.
    {
        int r = tid >> 2, sub = tid & 3;
        const float* ar = As + r * DDIM + sub * 32;
        float s = 0.f;
        #pragma unroll
        for (int i = 0; i < 32; i++) s += ar[i] * ar[i];
        sP[tid] = s;
    }
    __syncthreads();
    if (tid < TM) {
        float s = ((sP[tid * 4 + 0] + sP[tid * 4 + 1]) + sP[tid * 4 + 2]) + sP[tid * 4 + 3];
        sN[tid] = s;
    }
    __syncthreads();

    int ty = tid >> 4;   // 16 row-groups (4 rows each)
    int tx = tid & 15;   // 16 code-groups (8 codes each)
    const float* Ab = As + ty * 4 * DDIM;
    const float* Bb = Bs + tx * 8;

    float Sreg[4];
    #pragma unroll
    for (int m = 0; m < 4; m++) Sreg[m] = sN[ty * 4 + m];

    float best[4];
    int   bidx[4];
    #pragma unroll
    for (int m = 0; m < 4; m++) { best[m] = CUDART_INF_F; bidx[m] = 0x7fffffff; }

    for (int kc = 0; kc < KCODES; kc += KC) {
        __syncthreads();   // protect Bs from previous chunk's readers
        {
            float4* Bs4 = (float4*)Bs;
            #pragma unroll
            for (int i = 0; i < (DDIM * KC / 4) / NTHREADS; i++) {
                int idx4 = tid + i * NTHREADS;
                int d = idx4 >> 5, c4 = idx4 & 31;
                Bs4[idx4] = *(const float4*)(g_Bt + d * KCODES + kc + c4 * 4);
            }
        }
        __syncthreads();

        // packed accumulators: acc2[m][p] = codes (2p, 2p+1) of this 8-group.
        // Each 32-bit half is the SAME sequential k-ascending fp32 FMA chain
        // as the scalar version -- bit-identical numerics.
        unsigned long long acc2[4][4];
        #pragma unroll
        for (int m = 0; m < 4; m++)
            #pragma unroll
            for (int p = 0; p < 4; p++) acc2[m][p] = 0ull;

        #pragma unroll 2
        for (int d = 0; d < DDIM; d += 4) {
            float a[4][4];
            #pragma unroll
            for (int m = 0; m < 4; m++)
                *(float4*)a[m] = *(const float4*)(Ab + m * DDIM + d);
            #pragma unroll
            for (int dd = 0; dd < 4; dd++) {
                // float4 in memory [c0,c1,c2,c3] == ulonglong2 {(c0,c1),(c2,c3)}
                ulonglong2 bl = *(const ulonglong2*)(Bb + (d + dd) * KC);
                ulonglong2 bh = *(const ulonglong2*)(Bb + (d + dd) * KC + 4);
                #pragma unroll
                for (int m = 0; m < 4; m++) {
                    unsigned long long av2 = pack2(a[m][dd]);
                    acc2[m][0] = ffma2(av2, bl.x, acc2[m][0]);
                    acc2[m][1] = ffma2(av2, bl.y, acc2[m][1]);
                    acc2[m][2] = ffma2(av2, bh.x, acc2[m][2]);
                    acc2[m][3] = ffma2(av2, bh.y, acc2[m][3]);
                }
            }
        }

        // replicate reference rounding EXACTLY:
        //   d = fl32( fl32(||x||^2 + ||e||^2) - 2*dot )
        // __fadd_rn/__fsub_rn block FMA contraction. argmin, first-index ties.
        #pragma unroll
        for (int p = 0; p < 4; p++) {
            int kk0 = kc + tx * 8 + 2 * p;
            float cn0 = g_cnorm[kk0];
            float cn1 = g_cnorm[kk0 + 1];
            #pragma unroll
            for (int m = 0; m < 4; m++) {
                float d0, d1;
                unpack2(acc2[m][p], d0, d1);
                float dist0 = __fsub_rn(__fadd_rn(Sreg[m], cn0), 2.0f * d0);
                if (dist0 < best[m]) { best[m] = dist0; bidx[m] = kk0; }
                float dist1 = __fsub_rn(__fadd_rn(Sreg[m], cn1), 2.0f * d1);
                if (dist1 < best[m]) { best[m] = dist1; bidx[m] = kk0 + 1; }
            }
        }
    }

    // cross-tx argmin reduction (scratch in Bs region; As stays live)
    __syncthreads();
    float* rval = Bs;
    int* ridx   = (int*)(Bs + TM * 16);
    int* sbest  = (int*)(Bs + 2 * TM * 16);
    #pragma unroll
    for (int m = 0; m < 4; m++) {
        rval[(ty * 4 + m) * 16 + tx] = best[m];
        ridx[(ty * 4 + m) * 16 + tx] = bidx[m];
    }
    __syncthreads();
    if (tid < TM) {
        float bv = CUDART_INF_F; int bi = 0x7fffffff;
        #pragma unroll
        for (int t = 0; t < 16; t++) {
            float v = rval[tid * 16 + t];
            int ii  = ridx[tid * 16 + t];
            if (v < bv || (v == bv && ii < bi)) { bv = v; bi = ii; }
        }
        sbest[tid] = bi;
        atomicAdd(&g_counts[bi], 1);
    }
    __syncthreads();

    // gather codebook row, STE output x + (e - x), accumulate (e - x)^2
    int m   = tid >> 2;
    int sub = tid & 3;
    int brow = sbest[m];
    const float4* ev = (const float4*)(emb + (long long)brow * DDIM);
    const float4* xv = (const float4*)(As + m * DDIM);
    float4* ov = (float4*)(out + (row0 + m) * DDIM);
    float lsum = 0.f;
    #pragma unroll
    for (int i = sub; i < DDIM / 4; i += 4) {
        float4 e4 = __ldg(&ev[i]);
        float4 x4 = xv[i];
        float dx = e4.x - x4.x, dy = e4.y - x4.y;
        float dz = e4.z - x4.z, dw = e4.w - x4.w;
        ov[i] = make_float4(x4.x + dx, x4.y + dy, x4.z + dz, x4.w + dw);
        lsum += dx * dx + dy * dy + dz * dz + dw * dw;
    }
    // deterministic block reduction of loss partial
    #pragma unroll
    for (int o = 16; o > 0; o >>= 1) lsum += __shfl_xor_sync(0xffffffffu, lsum, o);
    if ((tid & 31) == 0) wsum[tid >> 5] = lsum;
    __syncthreads();
    if (tid == 0) {
        float s = 0.f;
        #pragma unroll
        for (int w = 0; w < 8; w++) s += wsum[w];
        g_partials[blockIdx.x] = s;
    }
}

// ---------------------------------------------------------------------------
// finalize: loss scalar + perplexity scalar
// grid = 1 block of 1024 threads
__global__ void vq_finalize(float* __restrict__ out, int n_elems, int N,
                            int blocks, int out_size) {
    __shared__ float buf[1024];
    int t = threadIdx.x;

    float s = 0.f;
    for (int i = t; i < blocks; i += 1024) s += g_partials[i];
    buf[t] = s;
    __syncthreads();
    #pragma unroll
    for (int o = 512; o > 0; o >>= 1) {
        if (t < o) buf[t] += buf[t + o];
        __syncthreads();
    }
    float lsum = buf[0];
    __syncthreads();

    float p = (float)g_counts[t] * (1.0f / (float)N);
    buf[t] = p * logf(p + 1e-10f);
    __syncthreads();
    #pragma unroll
    for (int o = 512; o > 0; o >>= 1) {
        if (t < o) buf[t] += buf[t + o];
        __syncthreads();
    }

    if (t == 0 && out_size >= n_elems + 2) {
        float mean = lsum / (float)n_elems;
        out[n_elems]     = mean + 0.25f * mean;   // q_latent + 0.25*e_latent
        out[n_elems + 1] = expf(-buf[0]);         // perplexity
    }
}

// ---------------------------------------------------------------------------
extern "C" void kernel_launch(void* const* d_in, const int* in_sizes, int n_in,
                              void* d_out, int out_size) {
    const float* x   = (const float*)d_in[0];   // inputs  [16,1024,512] f32
    const float* emb = (const float*)d_in[1];   // codebook [1024,128] f32
    float* out = (float*)d_out;

    int n_elems = in_sizes[0];        // 8388608
    int N = n_elems / DDIM;           // 65536 rows
    int blocks = N / TM;              // 1024

    size_t smem_bytes = (size_t)(TM * DDIM + DDIM * KC) * sizeof(float); // 96KB
    cudaFuncSetAttribute(vq_main, cudaFuncAttributeMaxDynamicSharedMemorySize,
                         (int)smem_bytes);

    vq_setup<<<KCODES, DDIM>>>(emb);
    vq_main<<<blocks, NTHREADS, smem_bytes>>>(x, emb, out, N);
    vq_finalize<<<1, 1024>>>(out, n_elems, N, blocks, out_size);
}

// round 14
// speedup vs baseline: 1.5391x; 1.5360x over previous
#include <cuda_runtime.h>
#include <cuda_bf16.h>
#include <math_constants.h>

#define DDIM   128
#define KCODES 1024
#define NROWS  65536
#define MARGIN 1.25e-4f

// ---------------- device scratch (no allocations allowed) -------------------
__device__ __align__(16) __nv_bfloat16 g_A[NROWS * 256];    // [row][xh(128)|xl(128)]
__device__ __align__(16) __nv_bfloat16 g_B[KCODES * 384];   // [code][eh|el|eh]
__device__ float          g_S[NROWS];                       // ||x||^2 exact structure
__device__ float          g_cnorm[KCODES];                  // ||e||^2 exact structure
__device__ int            g_counts[KCODES];
__device__ int            g_ccnt[NROWS];
__device__ unsigned short g_cand[NROWS * 16];
__device__ float          g_partials[8192];

// ---------------- ptx helpers ----------------------------------------------
__device__ __forceinline__ unsigned smaddr(const void* p) {
    return (unsigned)__cvta_generic_to_shared(p);
}
__device__ __forceinline__ void ldm_x4(unsigned& r0, unsigned& r1, unsigned& r2,
                                       unsigned& r3, unsigned a) {
    asm volatile("ldmatrix.sync.aligned.m8n8.x4.shared.b16 {%0,%1,%2,%3}, [%4];"
                 : "=r"(r0), "=r"(r1), "=r"(r2), "=r"(r3) : "r"(a));
}
__device__ __forceinline__ void ldm_x2(unsigned& r0, unsigned& r1, unsigned a) {
    asm volatile("ldmatrix.sync.aligned.m8n8.x2.shared.b16 {%0,%1}, [%2];"
                 : "=r"(r0), "=r"(r1) : "r"(a));
}
__device__ __forceinline__ void mma16816(float* c, const unsigned* a,
                                         unsigned b0, unsigned b1) {
    asm volatile(
        "mma.sync.aligned.m16n8k16.row.col.f32.bf16.bf16.f32 "
        "{%0,%1,%2,%3}, {%4,%5,%6,%7}, {%8,%9}, {%0,%1,%2,%3};"
        : "+f"(c[0]), "+f"(c[1]), "+f"(c[2]), "+f"(c[3])
        : "r"(a[0]), "r"(a[1]), "r"(a[2]), "r"(a[3]), "r"(b0), "r"(b1));
}
__device__ __forceinline__ unsigned long long pk(float d, int idx) {
    return ((unsigned long long)__float_as_uint(d) << 32) | (unsigned)idx;
}

// ---------------- prep: codebook split + norms + zero histogram -------------
// grid=(1024), block=(128). cnorm reduction structure matches the passing kernel.
__global__ void vq_prep_b(const float* __restrict__ emb) {
    int k = blockIdx.x, d = threadIdx.x;
    float v = emb[k * DDIM + d];
    __nv_bfloat16 h = __float2bfloat16(v);
    __nv_bfloat16 l = __float2bfloat16(v - __bfloat162float(h));
    g_B[k * 384 + d]       = h;   // eh
    g_B[k * 384 + 128 + d] = l;   // el
    g_B[k * 384 + 256 + d] = h;   // eh (paired with xl)
    float s = v * v;
    #pragma unroll
    for (int o = 16; o > 0; o >>= 1) s += __shfl_xor_sync(0xffffffffu, s, o);
    __shared__ float ws[4];
    if ((d & 31) == 0) ws[d >> 5] = s;
    __syncthreads();
    if (d == 0) {
        g_cnorm[k]  = (ws[0] + ws[1]) + (ws[2] + ws[3]);
        g_counts[k] = 0;
    }
}

// ---------------- prep: input split + exact row norms -----------------------
// grid=(65536), block=(128). S structure identical to the passing kernel.
__global__ void vq_prep_x(const float* __restrict__ x) {
    int r = blockIdx.x, d = threadIdx.x;
    __shared__ float sx[DDIM];
    __shared__ float sp[4];
    float v = x[(size_t)r * DDIM + d];
    sx[d] = v;
    __nv_bfloat16 h = __float2bfloat16(v);
    __nv_bfloat16 l = __float2bfloat16(v - __bfloat162float(h));
    g_A[(size_t)r * 256 + d]       = h;
    g_A[(size_t)r * 256 + 128 + d] = l;
    __syncthreads();
    if (d < 4) {
        float p = 0.f;
        #pragma unroll
        for (int i = 0; i < 32; i++) { float u = sx[d * 32 + i]; p += u * u; }
        sp[d] = p;
    }
    __syncthreads();
    if (d == 0) g_S[r] = ((sp[0] + sp[1]) + sp[2]) + sp[3];
}

// ---------------- tensor-core scoring + candidate collection ----------------
// grid=(512), block=(256)=8 warps (4m x 2n). CTA: 128 rows x 1024 codes, K=384.
#define ASTR 136   // padded bf16 row stride (272B): conflict-free ldmatrix
__global__ __launch_bounds__(256, 1) void vq_gemm() {
    extern __shared__ __align__(16) unsigned char dynsm[];
    __nv_bfloat16* Asm = reinterpret_cast<__nv_bfloat16*>(dynsm); // 2 parts [128][ASTR]
    __nv_bfloat16* Bsm = Asm + 2 * 128 * ASTR;                    // [256][ASTR]
    __shared__ float sS[128];
    __shared__ float sCN[256];
    __shared__ unsigned long long sMin[128];
    __shared__ unsigned short sCand[128 * 16];
    __shared__ int sCnt[128];

    int tid = threadIdx.x, lane = tid & 31, w = tid >> 5;
    int wy = w >> 1, wx = w & 1;
    int row0 = blockIdx.x * 128;

    if (tid < 128) { sS[tid] = g_S[row0 + tid]; sMin[tid] = ~0ull; sCnt[tid] = 0; }

    // A tile resident for whole kernel: both parts (xh, xl).
    // 128 rows x 16 uint4-segments per part = 2048 uint4 = 8 iters x 256 thr.
    #pragma unroll
    for (int p = 0; p < 2; p++)
        #pragma unroll
        for (int i = 0; i < 8; i++) {
            int idx = tid + i * 256, r = idx >> 4, seg = idx & 15;
            *(uint4*)(Asm + p * 128 * ASTR + r * ASTR + seg * 8) =
                *(const uint4*)(g_A + (size_t)(row0 + r) * 256 + p * 128 + seg * 8);
        }

    int tg = lane >> 2, tig = lane & 3;

    for (int nc = 0; nc < 4; nc++) {
        if (tid < 256) sCN[tid] = g_cnorm[nc * 256 + tid];

        float acc[2][16][4];
        #pragma unroll
        for (int i = 0; i < 2; i++)
            #pragma unroll
            for (int j = 0; j < 16; j++)
                #pragma unroll
                for (int e = 0; e < 4; e++) acc[i][j][e] = 0.f;

        for (int kc = 0; kc < 3; kc++) {
            __syncthreads();   // prev epilogue / prev B readers done
            // B chunk: codes [nc*256, +256), k part kc.
            // 256 rows x 16 uint4 = 4096 uint4 = 16 iters x 256 thr.
            #pragma unroll
            for (int i = 0; i < 16; i++) {
                int idx = tid + i * 256, r = idx >> 4, seg = idx & 15;
                *(uint4*)(Bsm + r * ASTR + seg * 8) =
                    *(const uint4*)(g_B + (size_t)(nc * 256 + r) * 384 + kc * 128 + seg * 8);
            }
            __syncthreads();

            const __nv_bfloat16* Ap = Asm + ((kc == 2) ? 1 : 0) * 128 * ASTR;
            #pragma unroll
            for (int ks = 0; ks < 8; ks++) {
                int k0 = ks * 16;
                unsigned afr[2][4];
                #pragma unroll
                for (int i = 0; i < 2; i++) {
                    unsigned a = smaddr(Ap + (wy * 32 + 16 * i + (lane & 15)) * ASTR
                                           + k0 + ((lane >> 4) << 3));
                    ldm_x4(afr[i][0], afr[i][1], afr[i][2], afr[i][3], a);
                }
                #pragma unroll
                for (int j = 0; j < 16; j++) {
                    unsigned b = smaddr(Bsm + (wx * 128 + 8 * j + (lane & 7)) * ASTR
                                            + k0 + (((lane >> 3) & 1) << 3));
                    unsigned b0, b1;
                    ldm_x2(b0, b1, b);
                    mma16816(acc[0][j], afr[0], b0, b1);
                    mma16816(acc[1][j], afr[1], b0, b1);
                }
            }
        }

        // ---- epilogue: approx dists, per-row packed min ----
        #pragma unroll
        for (int i = 0; i < 2; i++) {
            int ra = wy * 32 + 16 * i + tg, rb = ra + 8;
            float Sa = sS[ra], Sb = sS[rb];
            unsigned long long pka = ~0ull, pkb = ~0ull;
            #pragma unroll
            for (int j = 0; j < 16; j++) {
                int cl = wx * 128 + 8 * j + 2 * tig;
                int code = nc * 256 + cl;
                float cn0 = sCN[cl], cn1 = sCN[cl + 1];
                float d0 = __fsub_rn(__fadd_rn(Sa, cn0), 2.0f * acc[i][j][0]);
                float d1 = __fsub_rn(__fadd_rn(Sa, cn1), 2.0f * acc[i][j][1]);
                float d2 = __fsub_rn(__fadd_rn(Sb, cn0), 2.0f * acc[i][j][2]);
                float d3 = __fsub_rn(__fadd_rn(Sb, cn1), 2.0f * acc[i][j][3]);
                unsigned long long q;
                q = pk(d0, code);     if (q < pka) pka = q;
                q = pk(d1, code + 1); if (q < pka) pka = q;
                q = pk(d2, code);     if (q < pkb) pkb = q;
                q = pk(d3, code + 1); if (q < pkb) pkb = q;
            }
            #pragma unroll
            for (int o = 1; o <= 2; o <<= 1) {
                unsigned long long t;
                t = __shfl_xor_sync(0xffffffffu, pka, o); if (t < pka) pka = t;
                t = __shfl_xor_sync(0xffffffffu, pkb, o); if (t < pkb) pkb = t;
            }
            if (tig == 0) {
                atomicMin(&sMin[ra], pka);
                atomicMin(&sMin[rb], pkb);
            }
        }
        __syncthreads();

        // ---- candidate pass vs running min (safe: running >= final) ----
        #pragma unroll
        for (int i = 0; i < 2; i++) {
            int ra = wy * 32 + 16 * i + tg, rb = ra + 8;
            float Sa = sS[ra], Sb = sS[rb];
            float tha = __uint_as_float((unsigned)(sMin[ra] >> 32)) + MARGIN;
            float thb = __uint_as_float((unsigned)(sMin[rb] >> 32)) + MARGIN;
            #pragma unroll
            for (int j = 0; j < 16; j++) {
                int cl = wx * 128 + 8 * j + 2 * tig;
                int code = nc * 256 + cl;
                float cn0 = sCN[cl], cn1 = sCN[cl + 1];
                float d0 = __fsub_rn(__fadd_rn(Sa, cn0), 2.0f * acc[i][j][0]);
                float d1 = __fsub_rn(__fadd_rn(Sa, cn1), 2.0f * acc[i][j][1]);
                float d2 = __fsub_rn(__fadd_rn(Sb, cn0), 2.0f * acc[i][j][2]);
                float d3 = __fsub_rn(__fadd_rn(Sb, cn1), 2.0f * acc[i][j][3]);
                if (d0 <= tha) { int p2 = atomicAdd(&sCnt[ra], 1); if (p2 < 16) sCand[ra * 16 + p2] = (unsigned short)code; }
                if (d1 <= tha) { int p2 = atomicAdd(&sCnt[ra], 1); if (p2 < 16) sCand[ra * 16 + p2] = (unsigned short)(code + 1); }
                if (d2 <= thb) { int p2 = atomicAdd(&sCnt[rb], 1); if (p2 < 16) sCand[rb * 16 + p2] = (unsigned short)code; }
                if (d3 <= thb) { int p2 = atomicAdd(&sCnt[rb], 1); if (p2 < 16) sCand[rb * 16 + p2] = (unsigned short)(code + 1); }
            }
        }
        __syncthreads();
    }

    if (tid < 128) {
        g_ccnt[row0 + tid] = sCnt[tid];
        #pragma unroll
        for (int q = 0; q < 16; q++)
            g_cand[(size_t)(row0 + tid) * 16 + q] = sCand[tid * 16 + q];
    }
}

// ---------------- exact rescore + gather + STE + loss + histogram -----------
// grid=(8192), block=(256)=8 warps, 1 row per warp.
__global__ void vq_out(const float* __restrict__ x, const float* __restrict__ emb,
                       float* __restrict__ out) {
    __shared__ float sx[8][DDIM];
    __shared__ float rowloss[8];
    int tid = threadIdx.x, lane = tid & 31, w = tid >> 5;
    int row0 = blockIdx.x * 8;

    for (int idx = tid; idx < 8 * DDIM; idx += 256)
        sx[idx >> 7][idx & 127] = x[(size_t)row0 * DDIM + idx];
    __syncthreads();

    int row = row0 + w;
    // exact S: same structure as passing kernel
    float p = 0.f;
    if (lane < 4) {
        #pragma unroll
        for (int i = 0; i < 32; i++) { float u = sx[w][lane * 32 + i]; p += u * u; }
    }
    float p0 = __shfl_sync(0xffffffffu, p, 0);
    float p1 = __shfl_sync(0xffffffffu, p, 1);
    float p2 = __shfl_sync(0xffffffffu, p, 2);
    float p3 = __shfl_sync(0xffffffffu, p, 3);
    float S = ((p0 + p1) + p2) + p3;

    int cnt = g_ccnt[row];
    unsigned long long best = ~0ull;
    if (cnt >= 1 && cnt <= 16) {
        if (lane < cnt) {
            int code = g_cand[(size_t)row * 16 + lane];
            const float* e = emb + (size_t)code * DDIM;
            float dot = 0.f;
            #pragma unroll 4
            for (int k = 0; k < DDIM; k++) dot = fmaf(sx[w][k], __ldg(&e[k]), dot);
            float dist = __fsub_rn(__fadd_rn(S, g_cnorm[code]), 2.0f * dot);
            best = pk(dist, code);
        }
    } else {
        // overflow (or defensive empty-list) -> exact full scan, always correct
        for (int code = lane; code < KCODES; code += 32) {
            const float* e = emb + (size_t)code * DDIM;
            float dot = 0.f;
            #pragma unroll 4
            for (int k = 0; k < DDIM; k++) dot = fmaf(sx[w][k], __ldg(&e[k]), dot);
            float dist = __fsub_rn(__fadd_rn(S, g_cnorm[code]), 2.0f * dot);
            unsigned long long q = pk(dist, code);
            if (q < best) best = q;
        }
    }
    #pragma unroll
    for (int o = 16; o > 0; o >>= 1) {
        unsigned long long t = __shfl_xor_sync(0xffffffffu, best, o);
        if (t < best) best = t;
    }
    int code = (int)(unsigned)best;
    if (lane == 0) atomicAdd(&g_counts[code], 1);

    // output: out = x + (e - x); loss partial (e - x)^2
    const float4* e4p = (const float4*)(emb + (size_t)code * DDIM);
    const float4* x4p = (const float4*)(&sx[w][0]);
    float4* o4 = (float4*)(out + (size_t)row * DDIM);
    float4 e4 = __ldg(&e4p[lane]);
    float4 x4 = x4p[lane];
    float dx = e4.x - x4.x, dy = e4.y - x4.y, dz = e4.z - x4.z, dw = e4.w - x4.w;
    o4[lane] = make_float4(x4.x + dx, x4.y + dy, x4.z + dz, x4.w + dw);
    float ls = dx * dx + dy * dy + dz * dz + dw * dw;
    #pragma unroll
    for (int o = 16; o > 0; o >>= 1) ls += __shfl_xor_sync(0xffffffffu, ls, o);
    if (lane == 0) rowloss[w] = ls;
    __syncthreads();
    if (tid == 0) {
        float s = 0.f;
        #pragma unroll
        for (int i = 0; i < 8; i++) s += rowloss[i];
        g_partials[blockIdx.x] = s;
    }
}

// ---------------- finalize: loss + perplexity -------------------------------
__global__ void vq_finalize(float* __restrict__ out, int n_elems, int N,
                            int blocks, int out_size) {
    __shared__ float buf[1024];
    int t = threadIdx.x;
    float s = 0.f;
    for (int i = t; i < blocks; i += 1024) s += g_partials[i];
    buf[t] = s;
    __syncthreads();
    #pragma unroll
    for (int o = 512; o > 0; o >>= 1) {
        if (t < o) buf[t] += buf[t + o];
        __syncthreads();
    }
    float lsum = buf[0];
    __syncthreads();
    float pr = (float)g_counts[t] * (1.0f / (float)N);
    buf[t] = pr * logf(pr + 1e-10f);
    __syncthreads();
    #pragma unroll
    for (int o = 512; o > 0; o >>= 1) {
        if (t < o) buf[t] += buf[t + o];
        __syncthreads();
    }
    if (t == 0 && out_size >= n_elems + 2) {
        float mean = lsum / (float)n_elems;
        out[n_elems]     = mean + 0.25f * mean;
        out[n_elems + 1] = expf(-buf[0]);
    }
}

// ---------------------------------------------------------------------------
extern "C" void kernel_launch(void* const* d_in, const int* in_sizes, int n_in,
                              void* d_out, int out_size) {
    const float* x   = (const float*)d_in[0];   // [16,1024,512] f32
    const float* emb = (const float*)d_in[1];   // [1024,128] f32
    float* out = (float*)d_out;

    int n_elems = in_sizes[0];          // 8388608
    int N = n_elems / DDIM;             // 65536

    size_t gemm_smem = (size_t)(2 * 128 + 256) * ASTR * sizeof(__nv_bfloat16); // 139264
    cudaFuncSetAttribute(vq_gemm, cudaFuncAttributeMaxDynamicSharedMemorySize,
                         (int)gemm_smem);

    vq_prep_b<<<KCODES, 128>>>(emb);
    vq_prep_x<<<N, 128>>>(x);
    vq_gemm<<<N / 128, 256, gemm_smem>>>();
    vq_out<<<N / 8, 256>>>(x, emb, out);
    vq_finalize<<<1, 1024>>>(out, n_elems, N, N / 8, out_size);
}